// round 1
// baseline (speedup 1.0000x reference)
#include <cuda_runtime.h>
#include <math.h>

#define BB 64
#define DD 768
#define TT 512
#define GG 3072          // 4*DD
#define SVRC 1000.0f
#define SVRE 0.1f

// ---------------- scratch (device globals; allocation-free) ----------------
__device__ float g_gx[(size_t)TT * BB * GG];   // [t][b][j]  (x-part + biases)
__device__ float g_X [(size_t)BB * DD * TT];   // [b][d][t]  tanh(h), then l2-normed
__device__ float g_K [(size_t)BB * TT * TT];   // [b][t][s]  Gram
__device__ float g_h [2][BB * DD];             // ping-pong hidden state
__device__ float g_c [BB * DD];
__device__ float g_v [BB * TT];
__device__ float g_u [BB * TT];
__device__ float g_beta[2][BB * TT];
__device__ float g_eta[BB];
__device__ float g_w [BB * DD];

__device__ __forceinline__ float sigf(float x) { return 1.0f / (1.0f + expf(-x)); }

// ---------------- init: h0/c0 copy, beta=0, v=1 ----------------
__global__ void initKernel(const float* __restrict__ h0, const float* __restrict__ c0) {
    int i = blockIdx.x * blockDim.x + threadIdx.x;
    if (i < BB * DD) { g_h[0][i] = h0[i]; g_c[i] = c0[i]; }
    if (i < BB * TT) { g_beta[0][i] = 0.0f; g_v[i] = 1.0f; }
}

// ---------------- gx GEMM: gx[t][b][j] = sum_d inputs[b,d,t]*Wih[j,d] + bih[j]+bhh[j] ----
// grid (T/64, G/64, B), block 256, tile 64x64, BK=16, 4x4 per thread
__global__ void gxGemm(const float* __restrict__ inp, const float* __restrict__ Wih,
                       const float* __restrict__ bih, const float* __restrict__ bhh) {
    __shared__ float As[16][65];  // [k][t]
    __shared__ float Bs[16][65];  // [k][j]
    int b  = blockIdx.z;
    int t0 = blockIdx.x * 64, j0 = blockIdx.y * 64;
    int tid = threadIdx.x;
    int ty = tid >> 4, tx = tid & 15;
    float acc[4][4] = {};
    const float* Ab = inp + (size_t)b * DD * TT;
    for (int k0 = 0; k0 < DD; k0 += 16) {
#pragma unroll
        for (int i = 0; i < 4; i++) {
            int idx = tid + i * 256;
            int d = idx >> 6, t = idx & 63;
            As[d][t] = Ab[(size_t)(k0 + d) * TT + t0 + t];
        }
#pragma unroll
        for (int i = 0; i < 4; i++) {
            int idx = tid + i * 256;
            int j = idx >> 4, d = idx & 15;
            Bs[d][j] = Wih[(size_t)(j0 + j) * DD + k0 + d];
        }
        __syncthreads();
#pragma unroll
        for (int k = 0; k < 16; k++) {
            float a[4], bv[4];
#pragma unroll
            for (int i = 0; i < 4; i++) a[i]  = As[k][ty + 16 * i];
#pragma unroll
            for (int i = 0; i < 4; i++) bv[i] = Bs[k][tx + 16 * i];
#pragma unroll
            for (int i = 0; i < 4; i++)
#pragma unroll
                for (int j = 0; j < 4; j++) acc[i][j] += a[i] * bv[j];
        }
        __syncthreads();
    }
#pragma unroll
    for (int i = 0; i < 4; i++) {
        int t = t0 + ty + 16 * i;
#pragma unroll
        for (int j = 0; j < 4; j++) {
            int jj = j0 + tx + 16 * j;
            g_gx[((size_t)t * BB + b) * GG + jj] = acc[i][j] + bih[jj] + bhh[jj];
        }
    }
}

// ---------------- one LSTM step: gates = gx[t] + h @ Whh^T ; activations; h/c update ----
// grid (B/16, D/32) = (4,24), block 256. Each block: 16 b x 32 units x 4 gates.
// h double-buffered (read g_h[t&1], write g_h[(t&1)^1]) to avoid cross-block races.
__global__ void stepKernel(const float* __restrict__ Whh, int t) {
    __shared__ float Hs[32][18];    // [k][bb]           (row stride even -> float2 aligned)
    __shared__ float Ws[32][132];   // [k][uu*4+gate]    (row stride %4==0 -> float4 aligned)
    const float* hin  = g_h[t & 1];
    float*       hout = g_h[(t & 1) ^ 1];
    int b0 = blockIdx.x * 16;
    int u0 = blockIdx.y * 32;
    int tid = threadIdx.x;
    int uu = tid & 31;     // unit within tile (lane)
    int bq = tid >> 5;     // batch pair (warp id)
    float acc[2][4] = {};
    for (int k0 = 0; k0 < DD; k0 += 32) {
#pragma unroll
        for (int i = 0; i < 2; i++) {
            int idx = tid + i * 256;
            int k = idx & 31, bb = idx >> 5;
            Hs[k][bb] = hin[(size_t)(b0 + bb) * DD + k0 + k];
        }
#pragma unroll
        for (int i = 0; i < 16; i++) {
            int idx = tid + i * 256;
            int k = idx & 31, r = idx >> 5;   // r: 0..127
            int g = r >> 5, uw = r & 31;
            Ws[k][uw * 4 + g] = Whh[(size_t)(g * DD + u0 + uw) * DD + k0 + k];
        }
        __syncthreads();
#pragma unroll
        for (int k = 0; k < 32; k++) {
            float2 h2 = *(const float2*)&Hs[k][bq * 2];
            float4 w4 = *(const float4*)&Ws[k][uu * 4];
            acc[0][0] += h2.x * w4.x; acc[0][1] += h2.x * w4.y;
            acc[0][2] += h2.x * w4.z; acc[0][3] += h2.x * w4.w;
            acc[1][0] += h2.y * w4.x; acc[1][1] += h2.y * w4.y;
            acc[1][2] += h2.y * w4.z; acc[1][3] += h2.y * w4.w;
        }
        __syncthreads();
    }
#pragma unroll
    for (int bb = 0; bb < 2; bb++) {
        int b = b0 + bq * 2 + bb;
        int u = u0 + uu;
        size_t base = ((size_t)t * BB + b) * GG;
        float gi = g_gx[base + 0 * DD + u] + acc[bb][0];
        float gf = g_gx[base + 1 * DD + u] + acc[bb][1];
        float gg = g_gx[base + 2 * DD + u] + acc[bb][2];
        float go = g_gx[base + 3 * DD + u] + acc[bb][3];
        float co = g_c[(size_t)b * DD + u];
        float cn = sigf(gf) * co + sigf(gi) * tanhf(gg);
        float hn = sigf(go) * tanhf(cn);
        g_c[(size_t)b * DD + u] = cn;
        hout[(size_t)b * DD + u] = hn;
        g_X[((size_t)b * DD + u) * TT + t] = tanhf(hn);
    }
}

// ---------------- l2-normalize X over D (per b,t column) ----------------
__global__ void xNorm() {
    int b = blockIdx.x;
    int t = blockIdx.y * 128 + threadIdx.x;
    float* Xb = g_X + (size_t)b * DD * TT;
    float s = 0.f;
    for (int d = 0; d < DD; d++) { float x = Xb[(size_t)d * TT + t]; s += x * x; }
    float inv = 1.0f / sqrtf(s + 1e-12f);
    for (int d = 0; d < DD; d++) Xb[(size_t)d * TT + t] *= inv;
}

// ---------------- Gram: K[b][t][s] = sum_d X[b,d,t] X[b,d,s] (symmetric) ----------------
__global__ void gramKernel() {
    int b  = blockIdx.z;
    int t0 = blockIdx.x * 64, s0 = blockIdx.y * 64;
    if (s0 < t0) return;   // upper triangle only; mirror-write below
    __shared__ float As[16][65];
    __shared__ float Bs[16][65];
    const float* Xb = g_X + (size_t)b * DD * TT;
    int tid = threadIdx.x;
    int ty = tid >> 4, tx = tid & 15;
    float acc[4][4] = {};
    for (int k0 = 0; k0 < DD; k0 += 16) {
#pragma unroll
        for (int i = 0; i < 4; i++) {
            int idx = tid + i * 256;
            int d = idx >> 6, t = idx & 63;
            As[d][t] = Xb[(size_t)(k0 + d) * TT + t0 + t];
        }
#pragma unroll
        for (int i = 0; i < 4; i++) {
            int idx = tid + i * 256;
            int d = idx >> 6, scol = idx & 63;
            Bs[d][scol] = Xb[(size_t)(k0 + d) * TT + s0 + scol];
        }
        __syncthreads();
#pragma unroll
        for (int k = 0; k < 16; k++) {
            float a[4], bv[4];
#pragma unroll
            for (int i = 0; i < 4; i++) a[i]  = As[k][ty + 16 * i];
#pragma unroll
            for (int i = 0; i < 4; i++) bv[i] = Bs[k][tx + 16 * i];
#pragma unroll
            for (int i = 0; i < 4; i++)
#pragma unroll
                for (int j = 0; j < 4; j++) acc[i][j] += a[i] * bv[j];
        }
        __syncthreads();
    }
    float* Kb = g_K + (size_t)b * TT * TT;
#pragma unroll
    for (int i = 0; i < 4; i++) {
        int t = t0 + ty + 16 * i;
#pragma unroll
        for (int j = 0; j < 4; j++) {
            int sg = s0 + tx + 16 * j;
            Kb[(size_t)t * TT + sg] = acc[i][j];
            if (s0 > t0) Kb[(size_t)sg * TT + t] = acc[i][j];
        }
    }
}

// ---------------- batched GEMV: u = K v  (warp per row) ----------------
__global__ void gemvVU() {
    int b = blockIdx.y;
    int t = blockIdx.x * 8 + (threadIdx.x >> 5);
    int lane = threadIdx.x & 31;
    const float* Krow = g_K + ((size_t)b * TT + t) * TT;
    const float* vb = g_v + b * TT;
    float s = 0.f;
    for (int j = lane; j < TT; j += 32) s += Krow[j] * vb[j];
#pragma unroll
    for (int o = 16; o > 0; o >>= 1) s += __shfl_down_sync(0xffffffffu, s, o);
    if (lane == 0) g_u[b * TT + t] = s;
}

// v = u / (||u|| + 1e-12)
__global__ void vNormUV() {
    int b = blockIdx.x, tid = threadIdx.x;
    __shared__ float red[256];
    float s = 0.f;
    for (int t = tid; t < TT; t += 256) { float x = g_u[b * TT + t]; s += x * x; }
    red[tid] = s; __syncthreads();
    for (int o = 128; o > 0; o >>= 1) { if (tid < o) red[tid] += red[tid + o]; __syncthreads(); }
    float inv = 1.0f / (sqrtf(red[0]) + 1e-12f);
    for (int t = tid; t < TT; t += 256) g_v[b * TT + t] = g_u[b * TT + t] * inv;
}

// eta = 1/(1.01 * v^T u + 1e-6)   (after final u = K v)
__global__ void etaKernel() {
    int b = blockIdx.x, tid = threadIdx.x;
    __shared__ float red[256];
    float s = 0.f;
    for (int t = tid; t < TT; t += 256) s += g_v[b * TT + t] * g_u[b * TT + t];
    red[tid] = s; __syncthreads();
    for (int o = 128; o > 0; o >>= 1) { if (tid < o) red[tid] += red[tid + o]; __syncthreads(); }
    if (tid == 0) g_eta[b] = 1.0f / (1.01f * red[0] + 1e-6f);
}

// ---------------- one ISTA iteration, fused GEMV + soft-threshold (ping-pong beta) ----
__global__ void istaKernel(int p) {
    const float* bin = g_beta[p];
    float* bout = g_beta[p ^ 1];
    int b = blockIdx.y;
    int t = blockIdx.x * 8 + (threadIdx.x >> 5);
    int lane = threadIdx.x & 31;
    const float* Krow = g_K + ((size_t)b * TT + t) * TT;
    const float* bb = bin + b * TT;
    float s = 0.f;
    for (int j = lane; j < TT; j += 32) s += Krow[j] * bb[j];
#pragma unroll
    for (int o = 16; o > 0; o >>= 1) s += __shfl_down_sync(0xffffffffu, s, o);
    if (lane == 0) {
        float eta = g_eta[b];
        float grad = s - (float)(t + 1);
        float z = bb[t] - eta * grad;
        float az = fabsf(z) - eta * SVRE;
        float r = az > 0.f ? copysignf(az, z) : 0.f;
        r = fminf(fmaxf(r, -SVRC), SVRC);
        bout[b * TT + t] = r;
    }
}

// ---------------- w[b][d] = sum_t X[b,d,t] * beta[b,t] ----------------
__global__ void wKernel() {
    int b = blockIdx.y;
    int d = blockIdx.x * 8 + (threadIdx.x >> 5);
    int lane = threadIdx.x & 31;
    const float* Xr = g_X + ((size_t)b * DD + d) * TT;
    const float* be = g_beta[0] + b * TT;
    float s = 0.f;
    for (int t = lane; t < TT; t += 32) s += Xr[t] * be[t];
#pragma unroll
    for (int o = 16; o > 0; o >>= 1) s += __shfl_down_sync(0xffffffffu, s, o);
    if (lane == 0) g_w[b * DD + d] = s;
}

// ---------------- out = w / sqrt(||w||^2 + 1e-12) ----------------
__global__ void outNorm(float* __restrict__ out) {
    int b = blockIdx.x, tid = threadIdx.x;
    __shared__ float red[256];
    float s = 0.f;
    for (int d = tid; d < DD; d += 256) { float x = g_w[b * DD + d]; s += x * x; }
    red[tid] = s; __syncthreads();
    for (int o = 128; o > 0; o >>= 1) { if (tid < o) red[tid] += red[tid + o]; __syncthreads(); }
    float inv = 1.0f / sqrtf(red[0] + 1e-12f);
    for (int d = tid; d < DD; d += 256) out[b * DD + d] = g_w[b * DD + d] * inv;
}

// ---------------- launch ----------------
extern "C" void kernel_launch(void* const* d_in, const int* in_sizes, int n_in,
                              void* d_out, int out_size) {
    const float* inputs = (const float*)d_in[0];
    const float* h0     = (const float*)d_in[1];
    const float* c0     = (const float*)d_in[2];
    const float* Wih    = (const float*)d_in[3];
    const float* Whh    = (const float*)d_in[4];
    const float* bih    = (const float*)d_in[5];
    const float* bhh    = (const float*)d_in[6];
    float* out = (float*)d_out;

    initKernel<<<(BB * DD + 255) / 256, 256>>>(h0, c0);

    gxGemm<<<dim3(TT / 64, GG / 64, BB), 256>>>(inputs, Wih, bih, bhh);

    for (int t = 0; t < TT; t++)
        stepKernel<<<dim3(4, 24), 256>>>(Whh, t);

    xNorm<<<dim3(BB, TT / 128), 128>>>();

    gramKernel<<<dim3(TT / 64, TT / 64, BB), 256>>>();

    for (int it = 0; it < 20; it++) {
        gemvVU<<<dim3(TT / 8, BB), 256>>>();
        vNormUV<<<BB, 256>>>();
    }
    gemvVU<<<dim3(TT / 8, BB), 256>>>();
    etaKernel<<<BB, 256>>>();

    for (int it = 0; it < 200; it++)
        istaKernel<<<dim3(TT / 8, BB), 256>>>(it & 1);

    wKernel<<<dim3(DD / 8, BB), 256>>>();
    outNorm<<<BB, 256>>>(out);
}

// round 2
// speedup vs baseline: 1.3408x; 1.3408x over previous
#include <cuda_runtime.h>
#include <math.h>

#define BB 64
#define DD 768
#define TT 512
#define GG 3072          // 4*DD
#define SVRC 1000.0f
#define SVRE 0.1f
#define NBLK 96          // persistent LSTM grid (1 block/SM, <=148)

// ---------------- scratch (device globals; allocation-free) ----------------
__device__ float g_gx[(size_t)TT * BB * GG];   // [t][b][j]  (x-part + biases)
__device__ float g_X [(size_t)BB * DD * TT];   // [b][d][t]  tanh(h), then l2-normed
__device__ float g_K [(size_t)BB * TT * TT];   // [b][t][s]  Gram
__device__ float g_h [2][BB * DD];             // ping-pong hidden state
__device__ float g_c [BB * DD];
__device__ float g_v [BB * TT];
__device__ float g_u [BB * TT];
__device__ float g_beta[2][BB * TT];
__device__ float g_eta[BB];
__device__ float g_w [BB * DD];
__device__ int   g_cnt;
__device__ int   g_gen;

__device__ __forceinline__ float sigf(float x) { return 1.0f / (1.0f + expf(-x)); }

// ---------------- packed fp32x2 helpers (sm_100+) ----------------
__device__ __forceinline__ unsigned long long dup2(float x) {
    unsigned long long r; asm("mov.b64 %0, {%1, %1};" : "=l"(r) : "f"(x)); return r;
}
__device__ __forceinline__ void fma2(unsigned long long& acc, unsigned long long a, unsigned long long b) {
    asm("fma.rn.f32x2 %0, %1, %2, %0;" : "+l"(acc) : "l"(a), "l"(b));
}
__device__ __forceinline__ void add2(unsigned long long& acc, unsigned long long a) {
    asm("add.rn.f32x2 %0, %1, %0;" : "+l"(acc) : "l"(a));
}
__device__ __forceinline__ float2 unpk(unsigned long long v) {
    float2 f; asm("mov.b64 {%0, %1}, %2;" : "=f"(f.x), "=f"(f.y) : "l"(v)); return f;
}

// ---------------- init: h0/c0 copy, beta=0, v=1, barrier reset ----------------
__global__ void initKernel(const float* __restrict__ h0, const float* __restrict__ c0) {
    int i = blockIdx.x * blockDim.x + threadIdx.x;
    if (i == 0) { g_cnt = 0; g_gen = 0; }
    if (i < BB * DD) { g_h[0][i] = h0[i]; g_c[i] = c0[i]; }
    if (i < BB * TT) { g_beta[0][i] = 0.0f; g_v[i] = 1.0f; }
}

// ---------------- gx GEMM (f32x2): gx[t][b][j] = sum_d inp[b,d,t]*Wih[j,d] + biases ----
// grid (T/64, G/64, B), block 256, tile 64x64, BK=16, per-thread 4t x 4j (packed pairs)
__global__ void gxGemm(const float* __restrict__ inp, const float* __restrict__ Wih,
                       const float* __restrict__ bih, const float* __restrict__ bhh) {
    __shared__ float As[16][68];  // [k][t]  (stride 68 -> 16B aligned rows)
    __shared__ float Bs[16][68];  // [k][j]
    int b  = blockIdx.z;
    int t0 = blockIdx.x * 64, j0 = blockIdx.y * 64;
    int tid = threadIdx.x;
    int ty = tid >> 4, tx = tid & 15;
    unsigned long long acc[4][2] = {};
    const float* Ab = inp + (size_t)b * DD * TT;
    for (int k0 = 0; k0 < DD; k0 += 16) {
#pragma unroll
        for (int i = 0; i < 4; i++) {
            int idx = tid + i * 256;
            int d = idx >> 6, t = idx & 63;
            As[d][t] = Ab[(size_t)(k0 + d) * TT + t0 + t];
        }
#pragma unroll
        for (int i = 0; i < 4; i++) {
            int idx = tid + i * 256;
            int j = idx >> 4, d = idx & 15;
            Bs[d][j] = Wih[(size_t)(j0 + j) * DD + k0 + d];
        }
        __syncthreads();
#pragma unroll
        for (int k = 0; k < 16; k++) {
            float4 a4 = *(const float4*)&As[k][ty * 4];
            ulonglong2 b2 = *(const ulonglong2*)&Bs[k][tx * 4];
            unsigned long long d0 = dup2(a4.x), d1 = dup2(a4.y), d2 = dup2(a4.z), d3 = dup2(a4.w);
            fma2(acc[0][0], d0, b2.x); fma2(acc[0][1], d0, b2.y);
            fma2(acc[1][0], d1, b2.x); fma2(acc[1][1], d1, b2.y);
            fma2(acc[2][0], d2, b2.x); fma2(acc[2][1], d2, b2.y);
            fma2(acc[3][0], d3, b2.x); fma2(acc[3][1], d3, b2.y);
        }
        __syncthreads();
    }
    int j = j0 + tx * 4;
    float4 bi4 = *(const float4*)&bih[j];
    float4 bh4 = *(const float4*)&bhh[j];
#pragma unroll
    for (int i = 0; i < 4; i++) {
        int t = t0 + ty * 4 + i;
        float2 p0 = unpk(acc[i][0]);
        float2 p1 = unpk(acc[i][1]);
        float4 o;
        o.x = p0.x + bi4.x + bh4.x;
        o.y = p0.y + bi4.y + bh4.y;
        o.z = p1.x + bi4.z + bh4.z;
        o.w = p1.y + bi4.w + bh4.w;
        *(float4*)&g_gx[((size_t)t * BB + b) * GG + j] = o;
    }
}

// ---------------- persistent LSTM: all 512 steps in one kernel ----------------
// grid NBLK=96, 256 threads. Block r owns units u0=r*8..+8 (32 gate-rows).
// Whh slice resident in SMEM [768][36] (row = ul*4+g). h streamed via L2 (ldcg).
// Thread org: tid = q*64 + ug*16 + bg; q: k-quarter (32k of each 128k chunk),
// ug: 2 units (8 rows), bg: 4 batches. acc: 4b x 4 row-pairs in f32x2.
__global__ void __launch_bounds__(256, 1) lstmPersistent(const float* __restrict__ Whh) {
    extern __shared__ float sm[];
    float*  Ws  = sm;                               // [768][36] = 110592 B
    float4* Hs4 = (float4*)(sm + 768 * 36);         // [128][17] = 34816 B
    unsigned long long* red = (unsigned long long*)Hs4;  // reuse as reduce buffer

    int tid = threadIdx.x;
    int q  = tid >> 6;          // 0..3
    int ug = (tid >> 4) & 3;    // 0..3
    int bg = tid & 15;          // 0..15
    int u0 = blockIdx.x * 8;

    // fill Whh slice into SMEM (once)
    for (int r = 0; r < 32; r++) {
        int g = r & 3, ul = r >> 2;
        const float* src = Whh + (size_t)(g * DD + u0 + ul) * DD;
        for (int k = tid; k < DD; k += 256) Ws[k * 36 + r] = src[k];
    }

    // c state in registers (q==0 threads own epilogue)
    float cst[4][2];
    if (q == 0) {
#pragma unroll
        for (int bb = 0; bb < 4; bb++)
#pragma unroll
            for (int uu = 0; uu < 2; uu++)
                cst[bb][uu] = g_c[(size_t)(bg * 4 + bb) * DD + u0 + ug * 2 + uu];
    }

    for (int t = 0; t < TT; t++) {
        const float* hin  = g_h[t & 1];
        float*       hout = g_h[(t & 1) ^ 1];
        unsigned long long acc[4][4];
#pragma unroll
        for (int i = 0; i < 4; i++)
#pragma unroll
            for (int j = 0; j < 4; j++) acc[i][j] = 0ULL;

        for (int c6 = 0; c6 < 6; c6++) {
            int k0 = c6 * 128;
            __syncthreads();
            // fill Hs: [kk][bgrp] float4 of 4 batches, coalesced global reads (L2 only)
#pragma unroll
            for (int i = 0; i < 8; i++) {
                int idx = tid + i * 256;
                int kk = idx & 127, bq = idx >> 7;
                const float* hp = hin + (size_t)bq * 4 * DD + k0 + kk;
                float4 v;
                v.x = __ldcg(hp);
                v.y = __ldcg(hp + DD);
                v.z = __ldcg(hp + 2 * DD);
                v.w = __ldcg(hp + 3 * DD);
                Hs4[kk * 17 + bq] = v;
            }
            __syncthreads();
            int kb = q * 32;
#pragma unroll 8
            for (int i = 0; i < 32; i++) {
                int kk = kb + i;
                float4 h4 = Hs4[kk * 17 + bg];
                const float* wp = &Ws[(k0 + kk) * 36 + ug * 8];
                ulonglong2 wA = *(const ulonglong2*)wp;
                ulonglong2 wB = *(const ulonglong2*)(wp + 4);
                unsigned long long d0 = dup2(h4.x), d1 = dup2(h4.y), d2 = dup2(h4.z), d3 = dup2(h4.w);
                fma2(acc[0][0], d0, wA.x); fma2(acc[0][1], d0, wA.y);
                fma2(acc[0][2], d0, wB.x); fma2(acc[0][3], d0, wB.y);
                fma2(acc[1][0], d1, wA.x); fma2(acc[1][1], d1, wA.y);
                fma2(acc[1][2], d1, wB.x); fma2(acc[1][3], d1, wB.y);
                fma2(acc[2][0], d2, wA.x); fma2(acc[2][1], d2, wA.y);
                fma2(acc[2][2], d2, wB.x); fma2(acc[2][3], d2, wB.y);
                fma2(acc[3][0], d3, wA.x); fma2(acc[3][1], d3, wA.y);
                fma2(acc[3][2], d3, wB.x); fma2(acc[3][3], d3, wB.y);
            }
        }
        __syncthreads();
        // cross-quarter reduction through smem
        if (q != 0) {
            unsigned long long* rp = red + (size_t)(tid - 64) * 16;
#pragma unroll
            for (int bb = 0; bb < 4; bb++)
#pragma unroll
                for (int r = 0; r < 4; r++) rp[bb * 4 + r] = acc[bb][r];
        }
        __syncthreads();
        if (q == 0) {
#pragma unroll
            for (int j = 1; j < 4; j++) {
                unsigned long long* rp = red + (size_t)(j * 64 + ug * 16 + bg - 64) * 16;
#pragma unroll
                for (int bb = 0; bb < 4; bb++)
#pragma unroll
                    for (int r = 0; r < 4; r++) add2(acc[bb][r], rp[bb * 4 + r]);
            }
            size_t gxb = (size_t)t * BB * GG;
#pragma unroll
            for (int bb = 0; bb < 4; bb++) {
                int b = bg * 4 + bb;
#pragma unroll
                for (int uu = 0; uu < 2; uu++) {
                    int u = u0 + ug * 2 + uu;
                    float2 s01 = unpk(acc[bb][uu * 2]);      // (i, f)
                    float2 s23 = unpk(acc[bb][uu * 2 + 1]);  // (g, o)
                    const float* gp = g_gx + gxb + (size_t)b * GG + u;
                    float gi = __ldcg(gp)            + s01.x;
                    float gf = __ldcg(gp + DD)       + s01.y;
                    float gg = __ldcg(gp + 2 * DD)   + s23.x;
                    float go = __ldcg(gp + 3 * DD)   + s23.y;
                    float cn = sigf(gf) * cst[bb][uu] + sigf(gi) * tanhf(gg);
                    float hn = sigf(go) * tanhf(cn);
                    cst[bb][uu] = cn;
                    hout[(size_t)b * DD + u] = hn;
                    g_X[((size_t)b * DD + u) * TT + t] = tanhf(hn);
                }
            }
        }
        // ---- grid barrier (sense = step counter; g_gen reset by initKernel) ----
        __threadfence();
        __syncthreads();
        if (tid == 0) {
            if (atomicAdd(&g_cnt, 1) == NBLK - 1) {
                g_cnt = 0;
                __threadfence();
                *((volatile int*)&g_gen) = t + 1;
            } else {
                volatile int* vg = &g_gen;
                while (*vg <= t) {}
            }
        }
        __syncthreads();
    }
}

// ---------------- l2-normalize X over D (per b,t column) ----------------
__global__ void xNorm() {
    int b = blockIdx.x;
    int t = blockIdx.y * 128 + threadIdx.x;
    float* Xb = g_X + (size_t)b * DD * TT;
    float s = 0.f;
    for (int d = 0; d < DD; d++) { float x = Xb[(size_t)d * TT + t]; s += x * x; }
    float inv = 1.0f / sqrtf(s + 1e-12f);
    for (int d = 0; d < DD; d++) Xb[(size_t)d * TT + t] *= inv;
}

// ---------------- Gram: K[b][t][s] = sum_d X[b,d,t] X[b,d,s] (symmetric) ----------------
__global__ void gramKernel() {
    int b  = blockIdx.z;
    int t0 = blockIdx.x * 64, s0 = blockIdx.y * 64;
    if (s0 < t0) return;
    __shared__ float As[16][65];
    __shared__ float Bs[16][65];
    const float* Xb = g_X + (size_t)b * DD * TT;
    int tid = threadIdx.x;
    int ty = tid >> 4, tx = tid & 15;
    float acc[4][4] = {};
    for (int k0 = 0; k0 < DD; k0 += 16) {
#pragma unroll
        for (int i = 0; i < 4; i++) {
            int idx = tid + i * 256;
            int d = idx >> 6, t = idx & 63;
            As[d][t] = Xb[(size_t)(k0 + d) * TT + t0 + t];
        }
#pragma unroll
        for (int i = 0; i < 4; i++) {
            int idx = tid + i * 256;
            int d = idx >> 6, scol = idx & 63;
            Bs[d][scol] = Xb[(size_t)(k0 + d) * TT + s0 + scol];
        }
        __syncthreads();
#pragma unroll
        for (int k = 0; k < 16; k++) {
            float a[4], bv[4];
#pragma unroll
            for (int i = 0; i < 4; i++) a[i]  = As[k][ty + 16 * i];
#pragma unroll
            for (int i = 0; i < 4; i++) bv[i] = Bs[k][tx + 16 * i];
#pragma unroll
            for (int i = 0; i < 4; i++)
#pragma unroll
                for (int j = 0; j < 4; j++) acc[i][j] += a[i] * bv[j];
        }
        __syncthreads();
    }
    float* Kb = g_K + (size_t)b * TT * TT;
#pragma unroll
    for (int i = 0; i < 4; i++) {
        int t = t0 + ty + 16 * i;
#pragma unroll
        for (int j = 0; j < 4; j++) {
            int sg = s0 + tx + 16 * j;
            Kb[(size_t)t * TT + sg] = acc[i][j];
            if (s0 > t0) Kb[(size_t)sg * TT + t] = acc[i][j];
        }
    }
}

// ---------------- batched GEMV: u = K v  (warp per row) ----------------
__global__ void gemvVU() {
    int b = blockIdx.y;
    int t = blockIdx.x * 8 + (threadIdx.x >> 5);
    int lane = threadIdx.x & 31;
    const float* Krow = g_K + ((size_t)b * TT + t) * TT;
    const float* vb = g_v + b * TT;
    float s = 0.f;
    for (int j = lane; j < TT; j += 32) s += Krow[j] * vb[j];
#pragma unroll
    for (int o = 16; o > 0; o >>= 1) s += __shfl_down_sync(0xffffffffu, s, o);
    if (lane == 0) g_u[b * TT + t] = s;
}

// v = u / (||u|| + 1e-12)
__global__ void vNormUV() {
    int b = blockIdx.x, tid = threadIdx.x;
    __shared__ float red[256];
    float s = 0.f;
    for (int t = tid; t < TT; t += 256) { float x = g_u[b * TT + t]; s += x * x; }
    red[tid] = s; __syncthreads();
    for (int o = 128; o > 0; o >>= 1) { if (tid < o) red[tid] += red[tid + o]; __syncthreads(); }
    float inv = 1.0f / (sqrtf(red[0]) + 1e-12f);
    for (int t = tid; t < TT; t += 256) g_v[b * TT + t] = g_u[b * TT + t] * inv;
}

// eta = 1/(1.01 * v^T u + 1e-6)
__global__ void etaKernel() {
    int b = blockIdx.x, tid = threadIdx.x;
    __shared__ float red[256];
    float s = 0.f;
    for (int t = tid; t < TT; t += 256) s += g_v[b * TT + t] * g_u[b * TT + t];
    red[tid] = s; __syncthreads();
    for (int o = 128; o > 0; o >>= 1) { if (tid < o) red[tid] += red[tid + o]; __syncthreads(); }
    if (tid == 0) g_eta[b] = 1.0f / (1.01f * red[0] + 1e-6f);
}

// ---------------- one ISTA iteration, fused GEMV + soft-threshold ----------------
__global__ void istaKernel(int p) {
    const float* bin = g_beta[p];
    float* bout = g_beta[p ^ 1];
    int b = blockIdx.y;
    int t = blockIdx.x * 8 + (threadIdx.x >> 5);
    int lane = threadIdx.x & 31;
    const float* Krow = g_K + ((size_t)b * TT + t) * TT;
    const float* bb = bin + b * TT;
    float s = 0.f;
    for (int j = lane; j < TT; j += 32) s += Krow[j] * bb[j];
#pragma unroll
    for (int o = 16; o > 0; o >>= 1) s += __shfl_down_sync(0xffffffffu, s, o);
    if (lane == 0) {
        float eta = g_eta[b];
        float grad = s - (float)(t + 1);
        float z = bb[t] - eta * grad;
        float az = fabsf(z) - eta * SVRE;
        float r = az > 0.f ? copysignf(az, z) : 0.f;
        r = fminf(fmaxf(r, -SVRC), SVRC);
        bout[b * TT + t] = r;
    }
}

// ---------------- w[b][d] = sum_t X[b,d,t] * beta[b,t] ----------------
__global__ void wKernel() {
    int b = blockIdx.y;
    int d = blockIdx.x * 8 + (threadIdx.x >> 5);
    int lane = threadIdx.x & 31;
    const float* Xr = g_X + ((size_t)b * DD + d) * TT;
    const float* be = g_beta[0] + b * TT;
    float s = 0.f;
    for (int t = lane; t < TT; t += 32) s += Xr[t] * be[t];
#pragma unroll
    for (int o = 16; o > 0; o >>= 1) s += __shfl_down_sync(0xffffffffu, s, o);
    if (lane == 0) g_w[b * DD + d] = s;
}

// ---------------- out = w / sqrt(||w||^2 + 1e-12) ----------------
__global__ void outNorm(float* __restrict__ out) {
    int b = blockIdx.x, tid = threadIdx.x;
    __shared__ float red[256];
    float s = 0.f;
    for (int d = tid; d < DD; d += 256) { float x = g_w[b * DD + d]; s += x * x; }
    red[tid] = s; __syncthreads();
    for (int o = 128; o > 0; o >>= 1) { if (tid < o) red[tid] += red[tid + o]; __syncthreads(); }
    float inv = 1.0f / sqrtf(red[0] + 1e-12f);
    for (int d = tid; d < DD; d += 256) out[b * DD + d] = g_w[b * DD + d] * inv;
}

// ---------------- launch ----------------
extern "C" void kernel_launch(void* const* d_in, const int* in_sizes, int n_in,
                              void* d_out, int out_size) {
    const float* inputs = (const float*)d_in[0];
    const float* h0     = (const float*)d_in[1];
    const float* c0     = (const float*)d_in[2];
    const float* Wih    = (const float*)d_in[3];
    const float* Whh    = (const float*)d_in[4];
    const float* bih    = (const float*)d_in[5];
    const float* bhh    = (const float*)d_in[6];
    float* out = (float*)d_out;

    initKernel<<<(BB * DD + 255) / 256, 256>>>(h0, c0);

    gxGemm<<<dim3(TT / 64, GG / 64, BB), 256>>>(inputs, Wih, bih, bhh);

    const int smemSz = 768 * 36 * 4 + 128 * 17 * 16;   // Ws + Hs = 145408 B
    cudaFuncSetAttribute(lstmPersistent, cudaFuncAttributeMaxDynamicSharedMemorySize, smemSz);
    lstmPersistent<<<NBLK, 256, smemSz>>>(Whh);

    xNorm<<<dim3(BB, TT / 128), 128>>>();

    gramKernel<<<dim3(TT / 64, TT / 64, BB), 256>>>();

    for (int it = 0; it < 20; it++) {
        gemvVU<<<dim3(TT / 8, BB), 256>>>();
        vNormUV<<<BB, 256>>>();
    }
    gemvVU<<<dim3(TT / 8, BB), 256>>>();
    etaKernel<<<BB, 256>>>();

    for (int it = 0; it < 200; it++)
        istaKernel<<<dim3(TT / 8, BB), 256>>>(it & 1);

    wKernel<<<dim3(DD / 8, BB), 256>>>();
    outNorm<<<BB, 256>>>(out);
}

// round 3
// speedup vs baseline: 1.7117x; 1.2766x over previous
#include <cuda_runtime.h>
#include <math.h>

#define BB 64
#define DD 768
#define TT 512
#define GG 3072          // 4*DD
#define SVRC 1000.0f
#define SVRE 0.1f
#define NBLK 96          // persistent LSTM grid (1 block/SM)

typedef unsigned long long ull;

// ---------------- scratch (device globals; allocation-free) ----------------
__device__ float g_gx[(size_t)TT * BB * GG];   // [t][b][j]  (x-part + biases)
__device__ float g_X [(size_t)BB * DD * TT];   // [b][d][t]  tanh(h) (raw, NOT normalized)
__device__ float g_K [(size_t)BB * TT * TT];   // [b][t][s]  Gram (normalized)
__device__ float g_h [2][BB * DD];             // ping-pong hidden state
__device__ float g_c [BB * DD];
__device__ float g_invn[BB * TT];              // 1/||X[:,t]||
__device__ int   g_cnt;
__device__ int   g_gen;

__device__ __forceinline__ float sigf(float x) { return 1.0f / (1.0f + expf(-x)); }

// ---------------- packed fp32x2 helpers (sm_100+) ----------------
__device__ __forceinline__ ull dup2(float x) {
    ull r; asm("mov.b64 %0, {%1, %1};" : "=l"(r) : "f"(x)); return r;
}
__device__ __forceinline__ void fma2(ull& acc, ull a, ull b) {
    asm("fma.rn.f32x2 %0, %1, %2, %0;" : "+l"(acc) : "l"(a), "l"(b));
}
__device__ __forceinline__ void add2(ull& acc, ull a) {
    asm("add.rn.f32x2 %0, %1, %0;" : "+l"(acc) : "l"(a));
}
__device__ __forceinline__ float2 unpk(ull v) {
    float2 f; asm("mov.b64 {%0, %1}, %2;" : "=f"(f.x), "=f"(f.y) : "l"(v)); return f;
}

// ---------------- init ----------------
__global__ void initKernel(const float* __restrict__ h0, const float* __restrict__ c0) {
    int i = blockIdx.x * blockDim.x + threadIdx.x;
    if (i == 0) { g_cnt = 0; g_gen = 0; }
    if (i < BB * DD) { g_h[0][i] = h0[i]; g_c[i] = c0[i]; }
}

// ---------------- gx GEMM (f32x2) ----------------
__global__ void gxGemm(const float* __restrict__ inp, const float* __restrict__ Wih,
                       const float* __restrict__ bih, const float* __restrict__ bhh) {
    __shared__ float As[16][68];
    __shared__ float Bs[16][68];
    int b  = blockIdx.z;
    int t0 = blockIdx.x * 64, j0 = blockIdx.y * 64;
    int tid = threadIdx.x;
    int ty = tid >> 4, tx = tid & 15;
    ull acc[4][2] = {};
    const float* Ab = inp + (size_t)b * DD * TT;
    for (int k0 = 0; k0 < DD; k0 += 16) {
#pragma unroll
        for (int i = 0; i < 4; i++) {
            int idx = tid + i * 256;
            int d = idx >> 6, t = idx & 63;
            As[d][t] = Ab[(size_t)(k0 + d) * TT + t0 + t];
        }
#pragma unroll
        for (int i = 0; i < 4; i++) {
            int idx = tid + i * 256;
            int j = idx >> 4, d = idx & 15;
            Bs[d][j] = Wih[(size_t)(j0 + j) * DD + k0 + d];
        }
        __syncthreads();
#pragma unroll
        for (int k = 0; k < 16; k++) {
            float4 a4 = *(const float4*)&As[k][ty * 4];
            ulonglong2 b2 = *(const ulonglong2*)&Bs[k][tx * 4];
            ull d0 = dup2(a4.x), d1 = dup2(a4.y), d2 = dup2(a4.z), d3 = dup2(a4.w);
            fma2(acc[0][0], d0, b2.x); fma2(acc[0][1], d0, b2.y);
            fma2(acc[1][0], d1, b2.x); fma2(acc[1][1], d1, b2.y);
            fma2(acc[2][0], d2, b2.x); fma2(acc[2][1], d2, b2.y);
            fma2(acc[3][0], d3, b2.x); fma2(acc[3][1], d3, b2.y);
        }
        __syncthreads();
    }
    int j = j0 + tx * 4;
    float4 bi4 = *(const float4*)&bih[j];
    float4 bh4 = *(const float4*)&bhh[j];
#pragma unroll
    for (int i = 0; i < 4; i++) {
        int t = t0 + ty * 4 + i;
        float2 p0 = unpk(acc[i][0]);
        float2 p1 = unpk(acc[i][1]);
        float4 o;
        o.x = p0.x + bi4.x + bh4.x;
        o.y = p0.y + bi4.y + bh4.y;
        o.z = p1.x + bi4.z + bh4.z;
        o.w = p1.y + bi4.w + bh4.w;
        *(float4*)&g_gx[((size_t)t * BB + b) * GG + j] = o;
    }
}

// ---------------- persistent LSTM v2 ----------------
// 96 blocks x 256 threads. Block owns 8 units (32 gate rows), Whh slice in SMEM.
// tid = q*64 + ug*16 + bg.  acc[4 batches][4 row-pairs] f32x2 over 1/4 of K.
// Hs double-buffered (next chunk staged in regs during FMA). gx prefetched by all
// threads at step top. Epilogue spread across all 256 threads (2 (b,u) each).
#define WS_FLOATS  (768 * 36)                 // 27648
#define HS_FLOATS  (2 * 128 * 17 * 4)         // 17408
#define SMEM_FLOATS (WS_FLOATS + HS_FLOATS + 6144 + 2048)  // +red +sumb = 53248

__global__ void __launch_bounds__(256, 1) lstmPersistent(const float* __restrict__ Whh) {
    extern __shared__ float sm[];
    float*  Ws   = sm;
    float4* Hs4  = (float4*)(sm + WS_FLOATS);
    ull*    red  = (ull*)(sm + WS_FLOATS + HS_FLOATS);   // 192*16 ull
    ull*    sumb = red + 192 * 16;                        // 1024 ull

    int tid = threadIdx.x;
    int q  = tid >> 6;
    int ug = (tid >> 4) & 3;
    int bg = tid & 15;
    int u0 = blockIdx.x * 8;

    // Whh slice -> SMEM (once). row = ul*4+g at Ws[k*36 + row]
    for (int r = 0; r < 32; r++) {
        int g = r & 3, ul = r >> 2;
        const float* src = Whh + (size_t)(g * DD + u0 + ul) * DD;
        for (int k = tid; k < DD; k += 256) Ws[k * 36 + r] = src[k];
    }

    // distributed c-state: thread handles combos 2*tid, 2*tid+1 (combo = b*8 + ul)
    float cst[2];
#pragma unroll
    for (int j = 0; j < 2; j++) {
        int combo = tid * 2 + j;
        int b = combo >> 3, u = u0 + (combo & 7);
        cst[j] = g_c[(size_t)b * DD + u];
    }

    for (int t = 0; t < TT; t++) {
        const float* hin  = g_h[t & 1];
        float*       hout = g_h[(t & 1) ^ 1];

        // prefetch gx for this thread's epilogue combos (hidden behind compute)
        float px[2][4];
#pragma unroll
        for (int j = 0; j < 2; j++) {
            int combo = tid * 2 + j;
            int b = combo >> 3, u = u0 + (combo & 7);
            const float* gp = g_gx + ((size_t)t * BB + b) * GG + u;
            px[j][0] = __ldcg(gp);
            px[j][1] = __ldcg(gp + DD);
            px[j][2] = __ldcg(gp + 2 * DD);
            px[j][3] = __ldcg(gp + 3 * DD);
        }

        // fill chunk 0 into buffer 0
#pragma unroll
        for (int i = 0; i < 8; i++) {
            int idx = tid + i * 256;
            int kk = idx & 127, bq = idx >> 7;
            const float* hp = hin + (size_t)bq * 4 * DD + kk;
            float4 v;
            v.x = __ldcg(hp); v.y = __ldcg(hp + DD);
            v.z = __ldcg(hp + 2 * DD); v.w = __ldcg(hp + 3 * DD);
            Hs4[kk * 17 + bq] = v;
        }
        __syncthreads();

        ull acc[4][4];
#pragma unroll
        for (int i = 0; i < 4; i++)
#pragma unroll
            for (int j = 0; j < 4; j++) acc[i][j] = 0ULL;

        for (int c6 = 0; c6 < 6; c6++) {
            // stage next chunk's h in regs (latency overlapped with FMA below)
            float4 st[8];
            if (c6 < 5) {
                int k0n = (c6 + 1) * 128;
#pragma unroll
                for (int i = 0; i < 8; i++) {
                    int idx = tid + i * 256;
                    int kk = idx & 127, bq = idx >> 7;
                    const float* hp = hin + (size_t)bq * 4 * DD + k0n + kk;
                    st[i].x = __ldcg(hp); st[i].y = __ldcg(hp + DD);
                    st[i].z = __ldcg(hp + 2 * DD); st[i].w = __ldcg(hp + 3 * DD);
                }
            }
            int k0 = c6 * 128;
            const float4* Hc = Hs4 + (size_t)(c6 & 1) * (128 * 17);
            int kb = q * 32;
#pragma unroll 8
            for (int i = 0; i < 32; i++) {
                int kk = kb + i;
                float4 h4 = Hc[kk * 17 + bg];
                const float* wp = &Ws[(k0 + kk) * 36 + ug * 8];
                ulonglong2 wA = *(const ulonglong2*)wp;
                ulonglong2 wB = *(const ulonglong2*)(wp + 4);
                ull d0 = dup2(h4.x), d1 = dup2(h4.y), d2 = dup2(h4.z), d3 = dup2(h4.w);
                fma2(acc[0][0], d0, wA.x); fma2(acc[0][1], d0, wA.y);
                fma2(acc[0][2], d0, wB.x); fma2(acc[0][3], d0, wB.y);
                fma2(acc[1][0], d1, wA.x); fma2(acc[1][1], d1, wA.y);
                fma2(acc[1][2], d1, wB.x); fma2(acc[1][3], d1, wB.y);
                fma2(acc[2][0], d2, wA.x); fma2(acc[2][1], d2, wA.y);
                fma2(acc[2][2], d2, wB.x); fma2(acc[2][3], d2, wB.y);
                fma2(acc[3][0], d3, wA.x); fma2(acc[3][1], d3, wA.y);
                fma2(acc[3][2], d3, wB.x); fma2(acc[3][3], d3, wB.y);
            }
            if (c6 < 5) {
                float4* Hn = Hs4 + (size_t)((c6 + 1) & 1) * (128 * 17);
#pragma unroll
                for (int i = 0; i < 8; i++) {
                    int idx = tid + i * 256;
                    Hn[(idx & 127) * 17 + (idx >> 7)] = st[i];
                }
            }
            __syncthreads();
        }

        // cross-quarter reduction -> sumb (gate sums per combo)
        if (q != 0) {
            ull* rp = red + (size_t)(tid - 64) * 16;
#pragma unroll
            for (int bb = 0; bb < 4; bb++)
#pragma unroll
                for (int r = 0; r < 4; r++) rp[bb * 4 + r] = acc[bb][r];
        }
        __syncthreads();
        if (q == 0) {
#pragma unroll
            for (int j = 1; j < 4; j++) {
                ull* rp = red + (size_t)((j - 1) * 64 + tid) * 16;
#pragma unroll
                for (int bb = 0; bb < 4; bb++)
#pragma unroll
                    for (int r = 0; r < 4; r++) add2(acc[bb][r], rp[bb * 4 + r]);
            }
#pragma unroll
            for (int bb = 0; bb < 4; bb++)
#pragma unroll
                for (int r = 0; r < 4; r++) {
                    int combo = (bg * 4 + bb) * 8 + ug * 2 + (r >> 1);
                    sumb[combo * 2 + (r & 1)] = acc[bb][r];
                }
        }
        __syncthreads();

        // epilogue: all 256 threads, 2 combos each
#pragma unroll
        for (int j = 0; j < 2; j++) {
            int combo = tid * 2 + j;
            int b = combo >> 3, u = u0 + (combo & 7);
            float2 s01 = unpk(sumb[combo * 2]);       // (i, f)
            float2 s23 = unpk(sumb[combo * 2 + 1]);   // (g, o)
            float gi = px[j][0] + s01.x;
            float gf = px[j][1] + s01.y;
            float gg = px[j][2] + s23.x;
            float go = px[j][3] + s23.y;
            float cn = sigf(gf) * cst[j] + sigf(gi) * tanhf(gg);
            float hn = sigf(go) * tanhf(cn);
            cst[j] = cn;
            hout[(size_t)b * DD + u] = hn;
            g_X[((size_t)b * DD + u) * TT + t] = tanhf(hn);
        }

        // grid barrier
        __threadfence();
        __syncthreads();
        if (tid == 0) {
            if (atomicAdd(&g_cnt, 1) == NBLK - 1) {
                g_cnt = 0;
                __threadfence();
                *((volatile int*)&g_gen) = t + 1;
            } else {
                volatile int* vg = &g_gen;
                while (*vg <= t) {}
            }
        }
        __syncthreads();
    }
}

// ---------------- invn[b][t] = 1/sqrt(sum_d X^2 + 1e-12) ----------------
__global__ void normCol() {
    int b = blockIdx.x;
    int t = threadIdx.x;                   // 512 threads = TT
    const float* Xb = g_X + (size_t)b * DD * TT;
    float s = 0.f;
#pragma unroll 4
    for (int d = 0; d < DD; d++) { float x = Xb[(size_t)d * TT + t]; s += x * x; }
    g_invn[b * TT + t] = 1.0f / sqrtf(s + 1e-12f);
}

// ---------------- Gram with normalization folded into epilogue ----------------
__global__ void gramKernel() {
    int b  = blockIdx.z;
    int t0 = blockIdx.x * 64, s0 = blockIdx.y * 64;
    if (s0 < t0) return;
    __shared__ float As[16][65];
    __shared__ float Bs[16][65];
    const float* Xb = g_X + (size_t)b * DD * TT;
    int tid = threadIdx.x;
    int ty = tid >> 4, tx = tid & 15;
    float acc[4][4] = {};
    for (int k0 = 0; k0 < DD; k0 += 16) {
#pragma unroll
        for (int i = 0; i < 4; i++) {
            int idx = tid + i * 256;
            int d = idx >> 6, t = idx & 63;
            As[d][t] = Xb[(size_t)(k0 + d) * TT + t0 + t];
        }
#pragma unroll
        for (int i = 0; i < 4; i++) {
            int idx = tid + i * 256;
            int d = idx >> 6, scol = idx & 63;
            Bs[d][scol] = Xb[(size_t)(k0 + d) * TT + s0 + scol];
        }
        __syncthreads();
#pragma unroll
        for (int k = 0; k < 16; k++) {
            float a[4], bv[4];
#pragma unroll
            for (int i = 0; i < 4; i++) a[i]  = As[k][ty + 16 * i];
#pragma unroll
            for (int i = 0; i < 4; i++) bv[i] = Bs[k][tx + 16 * i];
#pragma unroll
            for (int i = 0; i < 4; i++)
#pragma unroll
                for (int j = 0; j < 4; j++) acc[i][j] += a[i] * bv[j];
        }
        __syncthreads();
    }
    float invt[4], invs[4];
#pragma unroll
    for (int i = 0; i < 4; i++) invt[i] = g_invn[b * TT + t0 + ty + 16 * i];
#pragma unroll
    for (int j = 0; j < 4; j++) invs[j] = g_invn[b * TT + s0 + tx + 16 * j];
    float* Kb = g_K + (size_t)b * TT * TT;
#pragma unroll
    for (int i = 0; i < 4; i++) {
        int t = t0 + ty + 16 * i;
#pragma unroll
        for (int j = 0; j < 4; j++) {
            int sg = s0 + tx + 16 * j;
            float v = acc[i][j] * invt[i] * invs[j];
            Kb[(size_t)t * TT + sg] = v;
            if (s0 > t0) Kb[(size_t)sg * TT + t] = v;
        }
    }
}

// ---------------- persistent per-batch solver: power + eta + ISTA + w + norm ----
// one block per batch, 512 threads (= TT). All vectors in SMEM, K from L2.
__global__ void __launch_bounds__(512, 1) solverKernel(float* __restrict__ out) {
    __shared__ float sv[TT], su[TT], sb0[TT], sb1[TT], sred[512], wbuf[DD];
    int b = blockIdx.x, tid = threadIdx.x;
    int wid = tid >> 5, lane = tid & 31;
    const float* Kb = g_K + (size_t)b * TT * TT;

    sv[tid] = 1.0f;
    sb0[tid] = 0.0f;
    __syncthreads();

    // power iterations: 20x {u = Kv; v = u/||u||}, then one more u = Kv
    for (int it = 0; it < 21; it++) {
        for (int rr = 0; rr < 32; rr++) {
            int row = wid * 32 + rr;
            const float* kr = Kb + (size_t)row * TT;
            float s = 0.f;
#pragma unroll
            for (int j = 0; j < 16; j++) s += kr[lane + j * 32] * sv[lane + j * 32];
#pragma unroll
            for (int o = 16; o > 0; o >>= 1) s += __shfl_down_sync(0xffffffffu, s, o);
            if (lane == 0) su[row] = s;
        }
        __syncthreads();
        if (it < 20) {
            float x = su[tid];
            sred[tid] = x * x;
            __syncthreads();
            for (int o = 256; o > 0; o >>= 1) { if (tid < o) sred[tid] += sred[tid + o]; __syncthreads(); }
            float inv = 1.0f / (sqrtf(sred[0]) + 1e-12f);
            __syncthreads();
            sv[tid] = su[tid] * inv;
            __syncthreads();
        }
    }
    // eta = 1/(1.01 * v.u + 1e-6)
    sred[tid] = sv[tid] * su[tid];
    __syncthreads();
    for (int o = 256; o > 0; o >>= 1) { if (tid < o) sred[tid] += sred[tid + o]; __syncthreads(); }
    float eta = 1.0f / (1.01f * sred[0] + 1e-6f);
    __syncthreads();

    // ISTA x 200 (ping-pong smem beta)
    float* bin = sb0; float* bout = sb1;
    for (int it = 0; it < 200; it++) {
        for (int rr = 0; rr < 32; rr++) {
            int row = wid * 32 + rr;
            const float* kr = Kb + (size_t)row * TT;
            float s = 0.f;
#pragma unroll
            for (int j = 0; j < 16; j++) s += kr[lane + j * 32] * bin[lane + j * 32];
#pragma unroll
            for (int o = 16; o > 0; o >>= 1) s += __shfl_down_sync(0xffffffffu, s, o);
            if (lane == 0) {
                float grad = s - (float)(row + 1);
                float z = bin[row] - eta * grad;
                float az = fabsf(z) - eta * SVRE;
                float r = az > 0.f ? copysignf(az, z) : 0.f;
                bout[row] = fminf(fmaxf(r, -SVRC), SVRC);
            }
        }
        __syncthreads();
        float* tmp = bin; bin = bout; bout = tmp;
    }

    // beta_scaled = beta * invn (into the free buffer)
    bout[tid] = bin[tid] * g_invn[b * TT + tid];
    __syncthreads();

    // w[d] = sum_t X[b,d,t] * beta_scaled[t]   (warp per row, 48 rows/warp)
    for (int rr = 0; rr < 48; rr++) {
        int d = wid * 48 + rr;
        const float* xr = g_X + ((size_t)b * DD + d) * TT;
        float s = 0.f;
#pragma unroll
        for (int j = 0; j < 16; j++) s += xr[lane + j * 32] * bout[lane + j * 32];
#pragma unroll
        for (int o = 16; o > 0; o >>= 1) s += __shfl_down_sync(0xffffffffu, s, o);
        if (lane == 0) wbuf[d] = s;
    }
    __syncthreads();

    // out = w / sqrt(||w||^2 + 1e-12)
    float s2 = wbuf[tid] * wbuf[tid];
    if (tid < DD - TT) s2 += wbuf[TT + tid] * wbuf[TT + tid];
    sred[tid] = s2;
    __syncthreads();
    for (int o = 256; o > 0; o >>= 1) { if (tid < o) sred[tid] += sred[tid + o]; __syncthreads(); }
    float inv = 1.0f / sqrtf(sred[0] + 1e-12f);
    out[(size_t)b * DD + tid] = wbuf[tid] * inv;
    if (tid < DD - TT) out[(size_t)b * DD + TT + tid] = wbuf[TT + tid] * inv;
}

// ---------------- launch ----------------
extern "C" void kernel_launch(void* const* d_in, const int* in_sizes, int n_in,
                              void* d_out, int out_size) {
    const float* inputs = (const float*)d_in[0];
    const float* h0     = (const float*)d_in[1];
    const float* c0     = (const float*)d_in[2];
    const float* Wih    = (const float*)d_in[3];
    const float* Whh    = (const float*)d_in[4];
    const float* bih    = (const float*)d_in[5];
    const float* bhh    = (const float*)d_in[6];
    float* out = (float*)d_out;

    initKernel<<<(BB * DD + 255) / 256, 256>>>(h0, c0);

    gxGemm<<<dim3(TT / 64, GG / 64, BB), 256>>>(inputs, Wih, bih, bhh);

    const int smemSz = SMEM_FLOATS * 4;   // 212992 B
    cudaFuncSetAttribute(lstmPersistent, cudaFuncAttributeMaxDynamicSharedMemorySize, smemSz);
    lstmPersistent<<<NBLK, 256, smemSz>>>(Whh);

    normCol<<<BB, TT>>>();

    gramKernel<<<dim3(TT / 64, TT / 64, BB), 256>>>();

    solverKernel<<<BB, TT>>>(out);
}

// round 4
// speedup vs baseline: 1.7158x; 1.0024x over previous
#include <cuda_runtime.h>
#include <math.h>

#define BB 64
#define DD 768
#define TT 512
#define GG 3072          // 4*DD
#define SVRC 1000.0f
#define SVRE 0.1f
#define NBLK 96          // persistent LSTM grid (1 block/SM, <=148 co-resident)

typedef unsigned long long ull;

// ---------------- scratch (device globals; allocation-free) ----------------
__device__ float g_gx[(size_t)TT * BB * GG];   // [t][b][j]  (x-part + biases)
__device__ float g_X [(size_t)BB * DD * TT];   // [b][d][t]  tanh(h) (raw, NOT normalized)
__device__ float g_K [(size_t)BB * TT * TT];   // [b][t][s]  Gram (normalized)
__device__ float g_h [2][BB * DD];             // ping-pong hidden state
__device__ float g_c [BB * DD];
__device__ float g_invn[BB * TT];              // 1/||X[:,t]||
__device__ int   g_cnt;
__device__ int   g_gen;

__device__ __forceinline__ float sigf(float x) { return 1.0f / (1.0f + expf(-x)); }

// ---------------- packed fp32x2 helpers (sm_100+) ----------------
__device__ __forceinline__ ull dup2(float x) {
    ull r; asm("mov.b64 %0, {%1, %1};" : "=l"(r) : "f"(x)); return r;
}
__device__ __forceinline__ void fma2(ull& acc, ull a, ull b) {
    asm("fma.rn.f32x2 %0, %1, %2, %0;" : "+l"(acc) : "l"(a), "l"(b));
}
__device__ __forceinline__ void add2(ull& acc, ull a) {
    asm("add.rn.f32x2 %0, %1, %0;" : "+l"(acc) : "l"(a));
}
__device__ __forceinline__ float2 unpk(ull v) {
    float2 f; asm("mov.b64 {%0, %1}, %2;" : "=f"(f.x), "=f"(f.y) : "l"(v)); return f;
}

// ---------------- init ----------------
__global__ void initKernel(const float* __restrict__ h0, const float* __restrict__ c0) {
    int i = blockIdx.x * blockDim.x + threadIdx.x;
    if (i == 0) { g_cnt = 0; g_gen = 0; }
    if (i < BB * DD) { g_h[0][i] = h0[i]; g_c[i] = c0[i]; }
}

// ---------------- gx GEMM (f32x2) ----------------
__global__ void gxGemm(const float* __restrict__ inp, const float* __restrict__ Wih,
                       const float* __restrict__ bih, const float* __restrict__ bhh) {
    __shared__ float As[16][68];
    __shared__ float Bs[16][68];
    int b  = blockIdx.z;
    int t0 = blockIdx.x * 64, j0 = blockIdx.y * 64;
    int tid = threadIdx.x;
    int ty = tid >> 4, tx = tid & 15;
    ull acc[4][2] = {};
    const float* Ab = inp + (size_t)b * DD * TT;
    for (int k0 = 0; k0 < DD; k0 += 16) {
#pragma unroll
        for (int i = 0; i < 4; i++) {
            int idx = tid + i * 256;
            int d = idx >> 6, t = idx & 63;
            As[d][t] = Ab[(size_t)(k0 + d) * TT + t0 + t];
        }
#pragma unroll
        for (int i = 0; i < 4; i++) {
            int idx = tid + i * 256;
            int j = idx >> 4, d = idx & 15;
            Bs[d][j] = Wih[(size_t)(j0 + j) * DD + k0 + d];
        }
        __syncthreads();
#pragma unroll
        for (int k = 0; k < 16; k++) {
            float4 a4 = *(const float4*)&As[k][ty * 4];
            ulonglong2 b2 = *(const ulonglong2*)&Bs[k][tx * 4];
            ull d0 = dup2(a4.x), d1 = dup2(a4.y), d2 = dup2(a4.z), d3 = dup2(a4.w);
            fma2(acc[0][0], d0, b2.x); fma2(acc[0][1], d0, b2.y);
            fma2(acc[1][0], d1, b2.x); fma2(acc[1][1], d1, b2.y);
            fma2(acc[2][0], d2, b2.x); fma2(acc[2][1], d2, b2.y);
            fma2(acc[3][0], d3, b2.x); fma2(acc[3][1], d3, b2.y);
        }
        __syncthreads();
    }
    int j = j0 + tx * 4;
    float4 bi4 = *(const float4*)&bih[j];
    float4 bh4 = *(const float4*)&bhh[j];
#pragma unroll
    for (int i = 0; i < 4; i++) {
        int t = t0 + ty * 4 + i;
        float2 p0 = unpk(acc[i][0]);
        float2 p1 = unpk(acc[i][1]);
        float4 o;
        o.x = p0.x + bi4.x + bh4.x;
        o.y = p0.y + bi4.y + bh4.y;
        o.z = p1.x + bi4.z + bh4.z;
        o.w = p1.y + bi4.w + bh4.w;
        *(float4*)&g_gx[((size_t)t * BB + b) * GG + j] = o;
    }
}

// ---------------- persistent LSTM v3: 512 threads, 4 warps/SMSP ----------------
// 96 blocks. Block owns 8 units (32 gate rows = rows r=ul*4+gate), Whh slice in SMEM.
// tid = q*128 + ug*16 + bg : q = k-quarter (32k of each 128 chunk), ug = unit 0..7,
// bg = batch-quad 0..15.  acc[4 batches][2 ull] = 4 gates of one unit, f32x2 packed.
// Hs double-buffered with register staging. Epilogue: 1 (b,u) combo per thread.
#define WS_FLOATS  (768 * 36)                 // 27648 floats = 110592 B
#define HS_FLOATS  (2 * 128 * 17 * 4)         // 17408 floats =  69632 B
#define RED_ULL    (384 * 8)                  //  3072 ull    =  24576 B
#define SUMB_ULL   (512 * 2)                  //  1024 ull    =   8192 B
#define SMEM_BYTES (WS_FLOATS * 4 + HS_FLOATS * 4 + RED_ULL * 8 + SUMB_ULL * 8) // 212992

__global__ void __launch_bounds__(512, 1) lstmPersistent(const float* __restrict__ Whh) {
    extern __shared__ float sm[];
    float*  Ws   = sm;
    float4* Hs4  = (float4*)(sm + WS_FLOATS);
    ull*    red  = (ull*)(sm + WS_FLOATS + HS_FLOATS);
    ull*    sumb = red + RED_ULL;

    int tid = threadIdx.x;
    int q  = tid >> 7;          // 0..3
    int ug = (tid >> 4) & 7;    // 0..7
    int bg = tid & 15;          // 0..15
    int u0 = blockIdx.x * 8;

    // Whh slice -> SMEM (once). row r = ul*4+g stored at Ws[k*36 + r]
    for (int r = 0; r < 32; r++) {
        int g = r & 3, ul = r >> 2;
        const float* src = Whh + (size_t)(g * DD + u0 + ul) * DD;
        for (int k = tid; k < DD; k += 512) Ws[k * 36 + r] = src[k];
    }

    // per-thread combo (b, u) for state + epilogue
    int cb = tid >> 3;
    int cu = u0 + (tid & 7);
    float cst = g_c[(size_t)cb * DD + cu];

    for (int t = 0; t < TT; t++) {
        const float* hin  = g_h[t & 1];
        float*       hout = g_h[(t & 1) ^ 1];

        // gx prefetch for this combo (consumed in epilogue; hidden behind compute)
        const float* gp = g_gx + ((size_t)t * BB + cb) * GG + cu;
        float pxi = __ldcg(gp);
        float pxf = __ldcg(gp + DD);
        float pxg = __ldcg(gp + 2 * DD);
        float pxo = __ldcg(gp + 3 * DD);

        // fill chunk 0 into buffer 0
#pragma unroll
        for (int i = 0; i < 4; i++) {
            int idx = tid + i * 512;
            int kk = idx & 127, bq = idx >> 7;
            const float* hp = hin + (size_t)bq * 4 * DD + kk;
            float4 v;
            v.x = __ldcg(hp); v.y = __ldcg(hp + DD);
            v.z = __ldcg(hp + 2 * DD); v.w = __ldcg(hp + 3 * DD);
            Hs4[kk * 17 + bq] = v;
        }
        __syncthreads();

        ull acc[4][2];
#pragma unroll
        for (int i = 0; i < 4; i++) { acc[i][0] = 0ULL; acc[i][1] = 0ULL; }

        for (int c6 = 0; c6 < 6; c6++) {
            float4 st[4];
            if (c6 < 5) {
                int k0n = (c6 + 1) * 128;
#pragma unroll
                for (int i = 0; i < 4; i++) {
                    int idx = tid + i * 512;
                    int kk = idx & 127, bq = idx >> 7;
                    const float* hp = hin + (size_t)bq * 4 * DD + k0n + kk;
                    st[i].x = __ldcg(hp); st[i].y = __ldcg(hp + DD);
                    st[i].z = __ldcg(hp + 2 * DD); st[i].w = __ldcg(hp + 3 * DD);
                }
            }
            int k0 = c6 * 128;
            const float4* Hc = Hs4 + (size_t)(c6 & 1) * (128 * 17);
            int kb = q * 32;
#pragma unroll 8
            for (int i = 0; i < 32; i++) {
                int kk = kb + i;
                float4 h4 = Hc[kk * 17 + bg];
                ulonglong2 wA = *(const ulonglong2*)&Ws[(k0 + kk) * 36 + ug * 4];
                ull d0 = dup2(h4.x), d1 = dup2(h4.y), d2 = dup2(h4.z), d3 = dup2(h4.w);
                fma2(acc[0][0], d0, wA.x); fma2(acc[0][1], d0, wA.y);
                fma2(acc[1][0], d1, wA.x); fma2(acc[1][1], d1, wA.y);
                fma2(acc[2][0], d2, wA.x); fma2(acc[2][1], d2, wA.y);
                fma2(acc[3][0], d3, wA.x); fma2(acc[3][1], d3, wA.y);
            }
            if (c6 < 5) {
                float4* Hn = Hs4 + (size_t)((c6 + 1) & 1) * (128 * 17);
#pragma unroll
                for (int i = 0; i < 4; i++) {
                    int idx = tid + i * 512;
                    Hn[(idx & 127) * 17 + (idx >> 7)] = st[i];
                }
            }
            __syncthreads();
        }

        // cross-quarter reduction: q>0 spill, q==0 accumulate
        if (q != 0) {
            ull* rp = red + (size_t)(tid - 128) * 8;
#pragma unroll
            for (int bb = 0; bb < 4; bb++) { rp[bb * 2] = acc[bb][0]; rp[bb * 2 + 1] = acc[bb][1]; }
        }
        __syncthreads();
        if (q == 0) {
#pragma unroll
            for (int j = 0; j < 3; j++) {
                ull* rp = red + (size_t)(j * 128 + tid) * 8;
#pragma unroll
                for (int bb = 0; bb < 4; bb++) { add2(acc[bb][0], rp[bb * 2]); add2(acc[bb][1], rp[bb * 2 + 1]); }
            }
#pragma unroll
            for (int bb = 0; bb < 4; bb++) {
                int combo = (bg * 4 + bb) * 8 + ug;
                sumb[combo * 2]     = acc[bb][0];
                sumb[combo * 2 + 1] = acc[bb][1];
            }
        }
        __syncthreads();

        // epilogue: all 512 threads, combo = tid
        {
            float2 s01 = unpk(sumb[tid * 2]);       // (i, f)
            float2 s23 = unpk(sumb[tid * 2 + 1]);   // (g, o)
            float gi = pxi + s01.x;
            float gf = pxf + s01.y;
            float gg = pxg + s23.x;
            float go = pxo + s23.y;
            float cn = sigf(gf) * cst + sigf(gi) * tanhf(gg);
            float hn = sigf(go) * tanhf(cn);
            cst = cn;
            hout[(size_t)cb * DD + cu] = hn;
            g_X[((size_t)cb * DD + cu) * TT + t] = tanhf(hn);
        }

        // grid barrier
        __threadfence();
        __syncthreads();
        if (tid == 0) {
            if (atomicAdd(&g_cnt, 1) == NBLK - 1) {
                g_cnt = 0;
                __threadfence();
                *((volatile int*)&g_gen) = t + 1;
            } else {
                volatile int* vg = &g_gen;
                while (*vg <= t) {}
            }
        }
        __syncthreads();
    }
}

// ---------------- invn[b][t] = 1/sqrt(sum_d X^2 + 1e-12) ----------------
__global__ void normCol() {
    int b = blockIdx.x;
    int t = threadIdx.x;                   // 512 threads = TT
    const float* Xb = g_X + (size_t)b * DD * TT;
    float s = 0.f;
#pragma unroll 4
    for (int d = 0; d < DD; d++) { float x = Xb[(size_t)d * TT + t]; s += x * x; }
    g_invn[b * TT + t] = 1.0f / sqrtf(s + 1e-12f);
}

// ---------------- Gram with normalization folded into epilogue ----------------
__global__ void gramKernel() {
    int b  = blockIdx.z;
    int t0 = blockIdx.x * 64, s0 = blockIdx.y * 64;
    if (s0 < t0) return;
    __shared__ float As[16][65];
    __shared__ float Bs[16][65];
    const float* Xb = g_X + (size_t)b * DD * TT;
    int tid = threadIdx.x;
    int ty = tid >> 4, tx = tid & 15;
    float acc[4][4] = {};
    for (int k0 = 0; k0 < DD; k0 += 16) {
#pragma unroll
        for (int i = 0; i < 4; i++) {
            int idx = tid + i * 256;
            int d = idx >> 6, t = idx & 63;
            As[d][t] = Xb[(size_t)(k0 + d) * TT + t0 + t];
        }
#pragma unroll
        for (int i = 0; i < 4; i++) {
            int idx = tid + i * 256;
            int d = idx >> 6, scol = idx & 63;
            Bs[d][scol] = Xb[(size_t)(k0 + d) * TT + s0 + scol];
        }
        __syncthreads();
#pragma unroll
        for (int k = 0; k < 16; k++) {
            float a[4], bv[4];
#pragma unroll
            for (int i = 0; i < 4; i++) a[i]  = As[k][ty + 16 * i];
#pragma unroll
            for (int i = 0; i < 4; i++) bv[i] = Bs[k][tx + 16 * i];
#pragma unroll
            for (int i = 0; i < 4; i++)
#pragma unroll
                for (int j = 0; j < 4; j++) acc[i][j] += a[i] * bv[j];
        }
        __syncthreads();
    }
    float invt[4], invs[4];
#pragma unroll
    for (int i = 0; i < 4; i++) invt[i] = g_invn[b * TT + t0 + ty + 16 * i];
#pragma unroll
    for (int j = 0; j < 4; j++) invs[j] = g_invn[b * TT + s0 + tx + 16 * j];
    float* Kb = g_K + (size_t)b * TT * TT;
#pragma unroll
    for (int i = 0; i < 4; i++) {
        int t = t0 + ty + 16 * i;
#pragma unroll
        for (int j = 0; j < 4; j++) {
            int sg = s0 + tx + 16 * j;
            float v = acc[i][j] * invt[i] * invs[j];
            Kb[(size_t)t * TT + sg] = v;
            if (s0 > t0) Kb[(size_t)sg * TT + t] = v;
        }
    }
}

// ---------------- persistent per-batch solver: power + eta + ISTA + w + norm ----
__global__ void __launch_bounds__(512, 1) solverKernel(float* __restrict__ out) {
    __shared__ float sv[TT], su[TT], sb0[TT], sb1[TT], sred[512], wbuf[DD];
    int b = blockIdx.x, tid = threadIdx.x;
    int wid = tid >> 5, lane = tid & 31;
    const float* Kb = g_K + (size_t)b * TT * TT;

    sv[tid] = 1.0f;
    sb0[tid] = 0.0f;
    __syncthreads();

    for (int it = 0; it < 21; it++) {
        for (int rr = 0; rr < 32; rr++) {
            int row = wid * 32 + rr;
            const float* kr = Kb + (size_t)row * TT;
            float s = 0.f;
#pragma unroll
            for (int j = 0; j < 16; j++) s += kr[lane + j * 32] * sv[lane + j * 32];
#pragma unroll
            for (int o = 16; o > 0; o >>= 1) s += __shfl_down_sync(0xffffffffu, s, o);
            if (lane == 0) su[row] = s;
        }
        __syncthreads();
        if (it < 20) {
            float x = su[tid];
            sred[tid] = x * x;
            __syncthreads();
            for (int o = 256; o > 0; o >>= 1) { if (tid < o) sred[tid] += sred[tid + o]; __syncthreads(); }
            float inv = 1.0f / (sqrtf(sred[0]) + 1e-12f);
            __syncthreads();
            sv[tid] = su[tid] * inv;
            __syncthreads();
        }
    }
    sred[tid] = sv[tid] * su[tid];
    __syncthreads();
    for (int o = 256; o > 0; o >>= 1) { if (tid < o) sred[tid] += sred[tid + o]; __syncthreads(); }
    float eta = 1.0f / (1.01f * sred[0] + 1e-6f);
    __syncthreads();

    float* bin = sb0; float* bout = sb1;
    for (int it = 0; it < 200; it++) {
        for (int rr = 0; rr < 32; rr++) {
            int row = wid * 32 + rr;
            const float* kr = Kb + (size_t)row * TT;
            float s = 0.f;
#pragma unroll
            for (int j = 0; j < 16; j++) s += kr[lane + j * 32] * bin[lane + j * 32];
#pragma unroll
            for (int o = 16; o > 0; o >>= 1) s += __shfl_down_sync(0xffffffffu, s, o);
            if (lane == 0) {
                float grad = s - (float)(row + 1);
                float z = bin[row] - eta * grad;
                float az = fabsf(z) - eta * SVRE;
                float r = az > 0.f ? copysignf(az, z) : 0.f;
                bout[row] = fminf(fmaxf(r, -SVRC), SVRC);
            }
        }
        __syncthreads();
        float* tmp = bin; bin = bout; bout = tmp;
    }

    bout[tid] = bin[tid] * g_invn[b * TT + tid];
    __syncthreads();

    for (int rr = 0; rr < 48; rr++) {
        int d = wid * 48 + rr;
        const float* xr = g_X + ((size_t)b * DD + d) * TT;
        float s = 0.f;
#pragma unroll
        for (int j = 0; j < 16; j++) s += xr[lane + j * 32] * bout[lane + j * 32];
#pragma unroll
        for (int o = 16; o > 0; o >>= 1) s += __shfl_down_sync(0xffffffffu, s, o);
        if (lane == 0) wbuf[d] = s;
    }
    __syncthreads();

    float s2 = wbuf[tid] * wbuf[tid];
    if (tid < DD - TT) s2 += wbuf[TT + tid] * wbuf[TT + tid];
    sred[tid] = s2;
    __syncthreads();
    for (int o = 256; o > 0; o >>= 1) { if (tid < o) sred[tid] += sred[tid + o]; __syncthreads(); }
    float inv = 1.0f / sqrtf(sred[0] + 1e-12f);
    out[(size_t)b * DD + tid] = wbuf[tid] * inv;
    if (tid < DD - TT) out[(size_t)b * DD + TT + tid] = wbuf[TT + tid] * inv;
}

// ---------------- launch ----------------
extern "C" void kernel_launch(void* const* d_in, const int* in_sizes, int n_in,
                              void* d_out, int out_size) {
    const float* inputs = (const float*)d_in[0];
    const float* h0     = (const float*)d_in[1];
    const float* c0     = (const float*)d_in[2];
    const float* Wih    = (const float*)d_in[3];
    const float* Whh    = (const float*)d_in[4];
    const float* bih    = (const float*)d_in[5];
    const float* bhh    = (const float*)d_in[6];
    float* out = (float*)d_out;

    initKernel<<<(BB * DD + 255) / 256, 256>>>(h0, c0);

    gxGemm<<<dim3(TT / 64, GG / 64, BB), 256>>>(inputs, Wih, bih, bhh);

    cudaFuncSetAttribute(lstmPersistent, cudaFuncAttributeMaxDynamicSharedMemorySize, SMEM_BYTES);
    lstmPersistent<<<NBLK, 512, SMEM_BYTES>>>(Whh);

    normCol<<<BB, TT>>>();

    gramKernel<<<dim3(TT / 64, TT / 64, BB), 256>>>();

    solverKernel<<<BB, TT>>>(out);
}